// round 4
// baseline (speedup 1.0000x reference)
#include <cuda_runtime.h>
#include <cuda_bf16.h>

#define NN 100000
#define NE 1600000
#define D  64
#define DO 32
#define NBLK 391            // ceil(NN/256)

// ---- scratch ----
__device__ int   g_deg[NN];
__device__ float g_dinv[NN];
__device__ int   g_ptr[NN + 1];
__device__ int   g_cursor[NN];
__device__ int   g_bsum[NBLK];
__device__ int   g_boff[NBLK];
__device__ int2  g_sw[NE];          // packed (src, weight-as-int)
__device__ float g_h1[NN * D];      // x @ W1
__device__ float g_agg1[NN * D];    // aggregated layer-1 (pre-bias/relu)
__device__ float g_h2[NN * DO];     // relu(agg1+b1) @ W2

// ------------------------------------------------------------------
// degree / dinv
// ------------------------------------------------------------------
__global__ void k_deg_init() {
    int i = blockIdx.x * blockDim.x + threadIdx.x;
    if (i < NN) g_deg[i] = 1;                // self-loop
}
__global__ void k_deg(const int* __restrict__ col) {
    int e = blockIdx.x * blockDim.x + threadIdx.x;
    if (e < NE) atomicAdd(&g_deg[col[e]], 1);
}
__global__ void k_dinv() {
    int i = blockIdx.x * blockDim.x + threadIdx.x;
    if (i < NN) g_dinv[i] = rsqrtf((float)g_deg[i]);
}

// ------------------------------------------------------------------
// exclusive scan of in-degree (deg-1) -> g_ptr, 3 kernels
// ------------------------------------------------------------------
__device__ __forceinline__ int warp_incl_scan(int v) {
    int lane = threadIdx.x & 31;
#pragma unroll
    for (int o = 1; o < 32; o <<= 1) {
        int t = __shfl_up_sync(0xffffffffu, v, o);
        if (lane >= o) v += t;
    }
    return v;
}

__global__ void k_scan1() {
    __shared__ int ws[8];
    int i = blockIdx.x * 256 + threadIdx.x;
    int v = (i < NN) ? (g_deg[i] - 1) : 0;
    int incl = warp_incl_scan(v);
    int lane = threadIdx.x & 31, w = threadIdx.x >> 5;
    if (lane == 31) ws[w] = incl;
    __syncthreads();
    if (threadIdx.x < 8) {
        int s = ws[threadIdx.x];
#pragma unroll
        for (int o = 1; o < 8; o <<= 1) {
            int t = __shfl_up_sync(0xffu, s, o);
            if (threadIdx.x >= o) s += t;
        }
        ws[threadIdx.x] = s;
    }
    __syncthreads();
    int off = w ? ws[w - 1] : 0;
    if (i < NN) g_ptr[i] = incl - v + off;
    if (threadIdx.x == 0) g_bsum[blockIdx.x] = ws[7];
}

__global__ void k_scan2() {
    __shared__ int ws[16];
    int i = threadIdx.x;                      // 512 threads
    int v = (i < NBLK) ? g_bsum[i] : 0;
    int incl = warp_incl_scan(v);
    int lane = i & 31, w = i >> 5;
    if (lane == 31) ws[w] = incl;
    __syncthreads();
    if (i < 16) {
        int s = ws[i];
#pragma unroll
        for (int o = 1; o < 16; o <<= 1) {
            int t = __shfl_up_sync(0xffffu, s, o);
            if (i >= o) s += t;
        }
        ws[i] = s;
    }
    __syncthreads();
    int off = w ? ws[w - 1] : 0;
    if (i < NBLK) g_boff[i] = incl - v + off;
}

__global__ void k_scan3() {
    int i = blockIdx.x * 256 + threadIdx.x;
    if (i < NN) {
        int p = g_ptr[i] + g_boff[blockIdx.x];
        g_ptr[i] = p;
        g_cursor[i] = p;
    }
    if (i == 0) g_ptr[NN] = NE;
}

// ------------------------------------------------------------------
// scatter edges into CSR buckets (packed src + edge weight)
// ------------------------------------------------------------------
__global__ void k_scatter(const int* __restrict__ row, const int* __restrict__ col) {
    int e = blockIdx.x * blockDim.x + threadIdx.x;
    if (e >= NE) return;
    int r = row[e], c = col[e];
    int pos = atomicAdd(&g_cursor[c], 1);
    g_sw[pos] = make_int2(r, __float_as_int(g_dinv[r] * g_dinv[c]));
}

// ------------------------------------------------------------------
// layer 1 GEMM: h1 = x @ W1
// ------------------------------------------------------------------
__global__ void k_gemm1(const float* __restrict__ x, const float* __restrict__ W1) {
    __shared__ float Ws[D * D];
    __shared__ float xs[4][D];
    int t = threadIdx.x;
    for (int i = t; i < D * D; i += 256) Ws[i] = W1[i];
    int ln = t >> 6, j = t & 63;
    int n = blockIdx.x * 4 + ln;
    xs[ln][j] = x[n * D + j];
    __syncthreads();
    float acc = 0.f;
#pragma unroll
    for (int k = 0; k < D; k++) acc = fmaf(xs[ln][k], Ws[k * D + j], acc);
    g_h1[n * D + j] = acc;
}

// ------------------------------------------------------------------
// layer 1 aggregation: warp per node, float2 per lane (64 cols)
// agg1[n] = dinv[n]^2 * h1[n] + sum_e w_e * h1[src_e]
// ------------------------------------------------------------------
__global__ void k_agg1() {
    int warp = blockIdx.x * 8 + (threadIdx.x >> 5);
    int l = threadIdx.x & 31;
    int beg = g_ptr[warp], end = g_ptr[warp + 1];
    float d = g_dinv[warp];
    float dd = d * d;
    float2 h = *(const float2*)&g_h1[warp * D + 2 * l];
    float2 acc = make_float2(dd * h.x, dd * h.y);
    int i = beg;
    for (; i + 1 < end; i += 2) {
        int2 sw0 = g_sw[i], sw1 = g_sw[i + 1];
        float w0 = __int_as_float(sw0.y), w1 = __int_as_float(sw1.y);
        float2 v0 = *(const float2*)&g_h1[sw0.x * D + 2 * l];
        float2 v1 = *(const float2*)&g_h1[sw1.x * D + 2 * l];
        acc.x = fmaf(w0, v0.x, acc.x); acc.y = fmaf(w0, v0.y, acc.y);
        acc.x = fmaf(w1, v1.x, acc.x); acc.y = fmaf(w1, v1.y, acc.y);
    }
    if (i < end) {
        int2 sw = g_sw[i];
        float w = __int_as_float(sw.y);
        float2 v = *(const float2*)&g_h1[sw.x * D + 2 * l];
        acc.x = fmaf(w, v.x, acc.x); acc.y = fmaf(w, v.y, acc.y);
    }
    *(float2*)&g_agg1[warp * D + 2 * l] = acc;
}

// ------------------------------------------------------------------
// layer 2 GEMM: z = relu(agg1 + b1); h2 = z @ W2
// ------------------------------------------------------------------
__global__ void k_gemm2(const float* __restrict__ W2, const float* __restrict__ b1) {
    __shared__ float Ws[D * DO];
    __shared__ float zs[8][D];
    int t = threadIdx.x;
    for (int i = t; i < D * DO; i += 256) Ws[i] = W2[i];
    int node0 = blockIdx.x * 8;
    for (int i = t; i < 8 * D; i += 256) {
        int nn = i >> 6, k = i & 63;
        zs[nn][k] = fmaxf(g_agg1[(node0 + nn) * D + k] + b1[k], 0.f);
    }
    __syncthreads();
    int ln = t >> 5, j = t & 31;
    int n = node0 + ln;
    float acc = 0.f;
#pragma unroll
    for (int k = 0; k < D; k++) acc = fmaf(zs[ln][k], Ws[k * DO + j], acc);
    g_h2[n * DO + j] = acc;
}

// ------------------------------------------------------------------
// layer 2 aggregation: warp per node, 1 float per lane (32 cols)
// ------------------------------------------------------------------
__global__ void k_agg2(float* __restrict__ out) {
    int warp = blockIdx.x * 8 + (threadIdx.x >> 5);
    int l = threadIdx.x & 31;
    int beg = g_ptr[warp], end = g_ptr[warp + 1];
    float d = g_dinv[warp];
    float acc = d * d * g_h2[warp * DO + l];
    int i = beg;
    for (; i + 1 < end; i += 2) {
        int2 sw0 = g_sw[i], sw1 = g_sw[i + 1];
        float v0 = g_h2[sw0.x * DO + l];
        float v1 = g_h2[sw1.x * DO + l];
        acc = fmaf(__int_as_float(sw0.y), v0, acc);
        acc = fmaf(__int_as_float(sw1.y), v1, acc);
    }
    if (i < end) {
        int2 sw = g_sw[i];
        acc = fmaf(__int_as_float(sw.y), g_h2[sw.x * DO + l], acc);
    }
    out[warp * DO + l] = acc;
}

// ------------------------------------------------------------------
// bias + log_softmax, one warp per node
// ------------------------------------------------------------------
__global__ void k_final(float* __restrict__ out, const float* __restrict__ b2) {
    int n = blockIdx.x * 8 + (threadIdx.x >> 5);
    int l = threadIdx.x & 31;
    float v = out[n * DO + l] + b2[l];
    float m = v;
#pragma unroll
    for (int o = 16; o; o >>= 1) m = fmaxf(m, __shfl_xor_sync(0xffffffffu, m, o));
    float s = expf(v - m);
#pragma unroll
    for (int o = 16; o; o >>= 1) s += __shfl_xor_sync(0xffffffffu, s, o);
    out[n * DO + l] = v - m - logf(s);
}

// ------------------------------------------------------------------
extern "C" void kernel_launch(void* const* d_in, const int* in_sizes, int n_in,
                              void* d_out, int out_size) {
    const float* x  = (const float*)d_in[0];
    const int*   ei = (const int*)d_in[1];
    const float* W1 = (const float*)d_in[2];
    const float* b1 = (const float*)d_in[3];
    const float* W2 = (const float*)d_in[4];
    const float* b2 = (const float*)d_in[5];
    float* out = (float*)d_out;

    const int* row = ei;
    const int* col = ei + NE;

    k_deg_init<<<NBLK, 256>>>();
    k_deg<<<(NE + 255) / 256, 256>>>(col);
    k_dinv<<<NBLK, 256>>>();

    k_scan1<<<NBLK, 256>>>();
    k_scan2<<<1, 512>>>();
    k_scan3<<<NBLK, 256>>>();
    k_scatter<<<(NE + 255) / 256, 256>>>(row, col);

    k_gemm1<<<NN / 4, 256>>>(x, W1);
    k_agg1<<<NN / 8, 256>>>();

    k_gemm2<<<NN / 8, 256>>>(W2, b1);
    k_agg2<<<NN / 8, 256>>>(out);

    k_final<<<NN / 8, 256>>>(out, b2);
}